// round 9
// baseline (speedup 1.0000x reference)
#include <cuda_runtime.h>
#include <cuda_bf16.h>
#include <cstdint>

#define BATCH 2048
#define RPB   16       // rows per MLP CTA
#define NCTA  128
#define NTHR  512      // 16 warps, each owns an 8-col N-slice
#define XCOLS 39
#define HID   128
#define WP    272      // W/A smem pitch bytes (136 bf16)

// ---- smem byte offsets ----
#define S0H 0
#define S0L 34816
#define S1H 69632
#define S1L 104448
#define E_H 139264     // emb A hi [16][WP]
#define E_L 143616
#define AAH 147968     // actA
#define AAL 152320
#define ABH 156672     // actB
#define ABL 161024
#define OHC 165376     // hc f32 [16][128]
#define OHB 173568     // hb f32 [16][128]
#define OW2 181760     // wc2bar [128][8] f32
#define OB1 185856     // bf1 [128]
#define OB2 186368     // bf2
#define OB3 186880     // bc1
#define OB4 187392     // bb1
#define OWB 187904     // Wb2
#define OBC 188416     // bc2bar[6], [6]=bb2
#define OCB 188448     // cbar [16][8]
#define OCF 188960     // coefB [16][4][4]
#define ORD 189984     // reduce partials [16][8][4] f32
#define MLP_SMEM 192032

// preconverted weights: [m][128][128] bf16, m = {f1(rows>=68 zero), f2, c1, b1}
__device__ __nv_bfloat16 g_whi[4 * 128 * 128];
__device__ __nv_bfloat16 g_wlo[4 * 128 * 128];
__device__ float g_wc2bar[128 * 8];

// ---------------- PTX wrappers ----------------
__device__ __forceinline__ void ldm4(uint32_t r[4], uint32_t a) {
    asm volatile("ldmatrix.sync.aligned.m8n8.x4.shared.b16 {%0,%1,%2,%3}, [%4];"
                 : "=r"(r[0]), "=r"(r[1]), "=r"(r[2]), "=r"(r[3]) : "r"(a));
}
__device__ __forceinline__ void ldm2t(uint32_t r[2], uint32_t a) {
    asm volatile("ldmatrix.sync.aligned.m8n8.x2.trans.shared.b16 {%0,%1}, [%2];"
                 : "=r"(r[0]), "=r"(r[1]) : "r"(a));
}
__device__ __forceinline__ void mma_bf16(float d[4], const uint32_t a[4],
                                         uint32_t b0, uint32_t b1) {
    asm("mma.sync.aligned.m16n8k16.row.col.f32.bf16.bf16.f32 "
        "{%0,%1,%2,%3}, {%4,%5,%6,%7}, {%8,%9}, {%0,%1,%2,%3};"
        : "+f"(d[0]), "+f"(d[1]), "+f"(d[2]), "+f"(d[3])
        : "r"(a[0]), "r"(a[1]), "r"(a[2]), "r"(a[3]), "r"(b0), "r"(b1));
}
__device__ __forceinline__ void split2(float v0, float v1, uint32_t& hi, uint32_t& lo) {
    __nv_bfloat162 h = __floats2bfloat162_rn(v0, v1);
    float f0 = __bfloat162float(h.x), f1 = __bfloat162float(h.y);
    __nv_bfloat162 g = __floats2bfloat162_rn(v0 - f0, v1 - f1);
    hi = *reinterpret_cast<uint32_t*>(&h);
    lo = *reinterpret_cast<uint32_t*>(&g);
}
__device__ __forceinline__ void cp16(uint32_t dst_smem, const void* src) {
    asm volatile("cp.async.cg.shared.global [%0], [%1], 16;\n" :: "r"(dst_smem), "l"(src));
}
#define CP_COMMIT() asm volatile("cp.async.commit_group;\n" ::: "memory")
#define CP_WAIT0()  asm volatile("cp.async.wait_group 0;\n" ::: "memory")
#define CP_WAIT1()  asm volatile("cp.async.wait_group 1;\n" ::: "memory")

// ---------------- weight preconvert kernel ----------------
__global__ __launch_bounds__(256) void convert_kernel(
    const float* __restrict__ Wf1, const float* __restrict__ Wf2,
    const float* __restrict__ Wc1, const float* __restrict__ Wb1,
    const float* __restrict__ Wc2)
{
    int tid = threadIdx.x;
    if (blockIdx.x < 64) {
        int idx = blockIdx.x * 256 + tid;      // 16384 float4 tasks
        int m = idx >> 12, r = idx & 4095;
        int k = r >> 5, n4 = (r & 31) * 4;
        float4 v = make_float4(0.f, 0.f, 0.f, 0.f);
        const float* src = (m == 0) ? Wf1 : (m == 1) ? Wf2 : (m == 2) ? Wc1 : Wb1;
        if (m != 0 || k < 68) v = *(const float4*)(src + k * 128 + n4);
        uint32_t h0, l0, h1, l1;
        split2(v.x, v.y, h0, l0);
        split2(v.z, v.w, h1, l1);
        int e = (m << 14) + k * 128 + n4;
        *(uint2*)((char*)g_whi + e * 2) = make_uint2(h0, h1);
        *(uint2*)((char*)g_wlo + e * 2) = make_uint2(l0, l1);
    } else if (tid < 128) {
        float s[6] = {0, 0, 0, 0, 0, 0};
        const float4* w4 = (const float4*)(Wc2 + tid * 48);
        #pragma unroll
        for (int v = 0; v < 12; v++) {
            float4 f = w4[v];
            s[(v * 4 + 0) % 6] += f.x; s[(v * 4 + 1) % 6] += f.y;
            s[(v * 4 + 2) % 6] += f.z; s[(v * 4 + 3) % 6] += f.w;
        }
        #pragma unroll
        for (int k = 0; k < 6; k++) g_wc2bar[tid * 8 + k] = s[k] * 0.125f;
        g_wc2bar[tid * 8 + 6] = 0.f; g_wc2bar[tid * 8 + 7] = 0.f;
    }
}

// stage preconverted matrix m into smem hi/lo tiles [rows][WP]
__device__ __forceinline__ void stage_pre(int m, char* smem, int offH, int offL,
                                          int rows, int tid)
{
    const char* sH = (const char*)(g_whi + (m << 14));
    const char* sL = (const char*)(g_wlo + (m << 14));
    uint32_t dH = (uint32_t)__cvta_generic_to_shared(smem + offH);
    uint32_t dL = (uint32_t)__cvta_generic_to_shared(smem + offL);
    int tot = rows * 16;
    for (int i = tid; i < tot; i += NTHR) {
        int k = i >> 4, n = (i & 15) * 16;
        cp16(dH + k * WP + n, sH + k * 256 + n);
        cp16(dL + k * WP + n, sL + k * 256 + n);
    }
}

// load A fragments (ks ksteps) from act buffer (broadcast to all warps)
__device__ __forceinline__ void loadA(uint32_t ahi[8][4], uint32_t alo[8][4],
                                      uint32_t bH, uint32_t bL, int ks, int lr, int lc)
{
    uint32_t base = lr * WP + lc * 2;
    for (int K = 0; K < ks; K++) {
        ldm4(ahi[K], bH + base + K * 32);
        ldm4(alo[K], bL + base + K * 32);
    }
}

// warp MMA over its 8-col N slice, 3-pass bf16
__device__ __forceinline__ void mma8(float acc[4],
                                     const uint32_t ahi[8][4], const uint32_t alo[8][4],
                                     uint32_t wH, uint32_t wL, int ks,
                                     int lr, uint32_t wcolb)
{
    for (int K = 0; K < ks; K++) {
        uint32_t ro = (uint32_t)((K * 16 + lr) * WP) + wcolb;
        uint32_t bh[2], bl[2];
        ldm2t(bh, wH + ro);
        ldm2t(bl, wL + ro);
        mma_bf16(acc, ahi[K], bh[0], bh[1]);
        mma_bf16(acc, ahi[K], bl[0], bl[1]);
        mma_bf16(acc, alo[K], bh[0], bh[1]);
    }
}

// bias+relu -> bf16 hi/lo act buffer (8-col slice); reset acc
__device__ __forceinline__ void epi_act(float acc[4], const float* __restrict__ bias,
                                        char* smem, int offH, int offL,
                                        int w, int lane)
{
    int r0 = lane >> 2, ql = lane & 3;
    int c = w * 8 + 2 * ql;
    float2 b = *(const float2*)(bias + c);
    float v0 = fmaxf(acc[0] + b.x, 0.f);
    float v1 = fmaxf(acc[1] + b.y, 0.f);
    float v2 = fmaxf(acc[2] + b.x, 0.f);
    float v3 = fmaxf(acc[3] + b.y, 0.f);
    uint32_t h0, l0, h1, l1;
    split2(v0, v1, h0, l0);
    split2(v2, v3, h1, l1);
    *(uint32_t*)(smem + offH + r0 * WP + c * 2)       = h0;
    *(uint32_t*)(smem + offL + r0 * WP + c * 2)       = l0;
    *(uint32_t*)(smem + offH + (r0 + 8) * WP + c * 2) = h1;
    *(uint32_t*)(smem + offL + (r0 + 8) * WP + c * 2) = l1;
    acc[0] = acc[1] = acc[2] = acc[3] = 0.f;
}

// bias+relu -> f32 buffer [16][128] (8-col slice); reset acc
__device__ __forceinline__ void epi_f32(float acc[4], const float* __restrict__ bias,
                                        float* __restrict__ dst, int w, int lane)
{
    int r0 = lane >> 2, ql = lane & 3;
    int c = w * 8 + 2 * ql;
    float2 b = *(const float2*)(bias + c);
    *(float2*)(dst + r0 * 128 + c)       = make_float2(fmaxf(acc[0] + b.x, 0.f),
                                                       fmaxf(acc[1] + b.y, 0.f));
    *(float2*)(dst + (r0 + 8) * 128 + c) = make_float2(fmaxf(acc[2] + b.x, 0.f),
                                                       fmaxf(acc[3] + b.y, 0.f));
    acc[0] = acc[1] = acc[2] = acc[3] = 0.f;
}

__global__ __launch_bounds__(NTHR, 1) void mlp_kernel(
    const float* __restrict__ x,
    const float* __restrict__ budget,
    const float* __restrict__ emb_id, const float* __restrict__ emb_period,
    const float* __restrict__ emb_time,
    const float* __restrict__ bf1, const float* __restrict__ bf2,
    const float* __restrict__ bc1, const float* __restrict__ bc2,
    const float* __restrict__ bb1, const float* __restrict__ Wb2,
    const float* __restrict__ bb2,
    float* __restrict__ out)
{
    extern __shared__ char smem[];
    float* smf = (float*)smem;
    const int tid  = threadIdx.x;
    const int w    = tid >> 5;
    const int lane = tid & 31;
    const int lr   = lane & 15;
    const int lc   = (lane >> 4) * 8;
    const int row0 = blockIdx.x * RPB;
    const uint32_t smb = (uint32_t)__cvta_generic_to_shared(smem);
    const uint32_t wcolb = (uint32_t)(w * 16);   // byte offset of warp's 8-col slice

    // ---- budget prefetch: independent of everything; hides behind the MLP ----
    const float4* bud4 = (const float4*)budget + row0 * 128;
    float4 pf[4];
    #pragma unroll
    for (int it = 0; it < 4; it++) pf[it] = bud4[tid + it * NTHR];

    // zero E hi/lo (covers zero-pad cols 68..79); 544 uint4
    for (int i = tid; i < 544; i += NTHR)
        ((uint4*)(smem + E_H))[i] = make_uint4(0, 0, 0, 0);

    // stage f1 (80 rows incl. zero rows) -> S0, f2 -> S1
    stage_pre(0, smem, S0H, S0L, 80, tid);  CP_COMMIT();
    stage_pre(1, smem, S1H, S1L, 128, tid); CP_COMMIT();

    // wc2bar copy, biases
    if (tid < 256)
        ((float4*)(smem + OW2))[tid] = ((const float4*)g_wc2bar)[tid];
    else if (tid < 384) {
        int t = tid - 256;
        smf[OB1 / 4 + t] = bf1[t];
        smf[OB2 / 4 + t] = bf2[t];
        smf[OB3 / 4 + t] = bc1[t];
        smf[OB4 / 4 + t] = bb1[t];
        smf[OWB / 4 + t] = Wb2[t];
    } else if (tid < 390) {
        int t = tid - 384;
        float s = 0.f;
        #pragma unroll
        for (int j = 0; j < 8; j++) s += bc2[j * 6 + t];
        smf[OBC / 4 + t] = s * 0.125f;
    } else if (tid == 390) {
        smf[OBC / 4 + 6] = bb2[0];
    }
    __syncthreads();   // E zeros visible before emb fill

    // emb fill: 16 rows x 68 cols, bf16 hi/lo
    for (int idx = tid; idx < RPB * 68; idx += NTHR) {
        int r = idx / 68, c = idx % 68;
        float v;
        if (c < 8) {
            v = emb_id[(int)x[(row0 + r) * XCOLS + 1] * 8 + c];
        } else if (c < 16) {
            v = emb_period[(int)x[(row0 + r) * XCOLS + 0] * 8 + (c - 8)];
        } else if (c < 32) {
            v = emb_time[(int)x[(row0 + r) * XCOLS + 2] * 16 + (c - 16)];
        } else {
            v = x[(row0 + r) * XCOLS + 3 + (c - 32)];
        }
        __nv_bfloat16 h = __float2bfloat16(v);
        __nv_bfloat16 l = __float2bfloat16(v - __bfloat162float(h));
        *(__nv_bfloat16*)(smem + E_H + r * WP + c * 2) = h;
        *(__nv_bfloat16*)(smem + E_L + r * WP + c * 2) = l;
    }
    CP_WAIT1();        // f1 arrived
    __syncthreads();   // emb visible

    float acc[4];
    acc[0] = acc[1] = acc[2] = acc[3] = 0.f;
    uint32_t ahi[8][4], alo[8][4];

    // ---- L1: E x Wf1(S0) -> actA ----
    loadA(ahi, alo, smb + E_H, smb + E_L, 5, lr, lc);
    mma8(acc, ahi, alo, smb + S0H, smb + S0L, 5, lr, wcolb);
    epi_act(acc, smf + OB1 / 4, smem, AAH, AAL, w, lane);
    CP_WAIT0();        // f2 arrived
    __syncthreads();   // actA visible, S0 free

    // ---- L2: actA x Wf2(S1) -> actB;  prefetch c1 -> S0 ----
    stage_pre(2, smem, S0H, S0L, 128, tid); CP_COMMIT();
    loadA(ahi, alo, smb + AAH, smb + AAL, 8, lr, lc);
    mma8(acc, ahi, alo, smb + S1H, smb + S1L, 8, lr, wcolb);
    epi_act(acc, smf + OB2 / 4, smem, ABH, ABL, w, lane);
    __syncthreads();   // actB visible, S1 free

    // ---- prefetch b1 -> S1; L3: actB x Wc1(S0) -> hc ----
    stage_pre(3, smem, S1H, S1L, 128, tid); CP_COMMIT();
    CP_WAIT1();        // c1 arrived
    loadA(ahi, alo, smb + ABH, smb + ABL, 8, lr, lc);
    mma8(acc, ahi, alo, smb + S0H, smb + S0L, 8, lr, wcolb);
    epi_f32(acc, smf + OB3 / 4, smf + OHC / 4, w, lane);

    // ---- L4: actB x Wb1(S1) -> hb (same A frags) ----
    CP_WAIT0();        // b1 arrived
    mma8(acc, ahi, alo, smb + S1H, smb + S1L, 8, lr, wcolb);
    epi_f32(acc, smf + OB4 / 4, smf + OHB / 4, w, lane);
    __syncthreads();

    // ---- final dots, parallel: (rb 16) x (slot 8) x (quarter 4) ----
    {
        int rb = tid >> 5, rem = tid & 31;
        int slot = rem >> 2, q = rem & 3;
        float s = 0.f;
        if (slot < 6) {
            const float* hc = smf + OHC / 4 + rb * 128 + q * 32;
            const float* wz = smf + OW2 / 4 + q * 32 * 8 + slot;
            #pragma unroll 8
            for (int i = 0; i < 32; i++) s += hc[i] * wz[i * 8];
        } else if (slot == 6) {
            const float* hb = smf + OHB / 4 + rb * 128 + q * 32;
            const float* wb = smf + OWB / 4 + q * 32;
            #pragma unroll 8
            for (int i = 0; i < 32; i++) s += hb[i] * wb[i];
        }
        smf[ORD / 4 + (rb * 8 + slot) * 4 + q] = s;
    }
    __syncthreads();
    if (tid < 128) {
        int rb = tid >> 3, slot = tid & 7;
        const float* r = smf + ORD / 4 + (rb * 8 + slot) * 4;
        if (slot < 6)
            smf[OCB / 4 + rb * 8 + slot] = r[0] + r[1] + r[2] + r[3] + smf[OBC / 4 + slot];
        else if (slot == 6)
            smf[OCB / 4 + rb * 8 + 6] = r[0] + r[1] + r[2] + r[3] + smf[OBC / 4 + 6];
    }
    __syncthreads();

    // ---- per-row piecewise cubic in X ----
    if (tid < 48) {
        int rb = tid / 3, m = tid - rb * 3;
        const float* c = smf + OCB / 4 + rb * 8 + m;
        float c0 = c[0], c1 = c[1], c2 = c[2], c3 = c[3];
        const float k6 = 1.f / 6.f;
        float A0 = (c0 + 4.f * c1 + c2) * k6;
        float A1 = (c2 - c0) * 0.5f;
        float A2 = (c0 - 2.f * c1 + c2) * 0.5f;
        float A3 = (c3 - c0 + 3.f * (c1 - c2)) * k6;
        float d  = 1.5f - (float)m;
        float B0 = A0 + d * (A1 + d * (A2 + d * A3));
        float B1 = 1.5f * (A1 + d * (2.f * A2 + 3.f * A3 * d));
        float B2 = 2.25f * (A2 + 3.f * A3 * d);
        float B3 = 3.375f * A3;
        ((float4*)(smem + OCF))[rb * 4 + m] = make_float4(B0, B1, B2, B3);
    }
    __syncthreads();

    // ---- budget phase: data already in pf[] registers ----
    float4* out4 = (float4*)out + row0 * 128;
    const float4* cb4 = (const float4*)(smem + OCF);
    #pragma unroll
    for (int it = 0; it < 4; it++) {
        int q = tid + it * NTHR;
        int row = q >> 7;
        float4 bv = pf[it];
        float sb = smf[OCB / 4 + row * 8 + 6];
        float xs[4] = {bv.x, bv.y, bv.z, bv.w};
        float o[4];
        #pragma unroll
        for (int e = 0; e < 4; e++) {
            float X = xs[e];
            float tp = fmaf(X, 1.5f, 1.5f);
            int m = min((int)tp, 2);
            float4 B = cb4[row * 4 + m];
            float sp = fmaf(fmaf(fmaf(B.w, X, B.z), X, B.y), X, B.x);
            float u = X * X;
            float P = fmaf(u, fmaf(u, fmaf(u, fmaf(u, 2.1357286e-5f, -2.1081349e-4f),
                                           2.0833333e-3f), -2.0833333e-2f), 0.25f);
            float sil = X * fmaf(X, P, 0.5f);
            o[e] = sb * (sil + sp);
        }
        out4[q] = make_float4(o[0], o[1], o[2], o[3]);
    }
}

extern "C" void kernel_launch(void* const* d_in, const int* in_sizes, int n_in,
                              void* d_out, int out_size)
{
    const float* x          = (const float*)d_in[0];
    const float* budget     = (const float*)d_in[1];
    const float* emb_id     = (const float*)d_in[2];
    const float* emb_period = (const float*)d_in[3];
    const float* emb_time   = (const float*)d_in[4];
    const float* Wf1 = (const float*)d_in[5];
    const float* bf1 = (const float*)d_in[6];
    const float* Wf2 = (const float*)d_in[7];
    const float* bf2 = (const float*)d_in[8];
    const float* Wc1 = (const float*)d_in[9];
    const float* bc1 = (const float*)d_in[10];
    const float* Wc2 = (const float*)d_in[11];
    const float* bc2 = (const float*)d_in[12];
    // d_in[13..16] = Ws1/bs1/Ws2/bs2 : unused in reference output
    const float* Wb1 = (const float*)d_in[17];
    const float* bb1 = (const float*)d_in[18];
    const float* Wb2 = (const float*)d_in[19];
    const float* bb2 = (const float*)d_in[20];

    cudaFuncSetAttribute(mlp_kernel, cudaFuncAttributeMaxDynamicSharedMemorySize, MLP_SMEM);

    convert_kernel<<<65, 256>>>(Wf1, Wf2, Wc1, Wb1, Wc2);
    mlp_kernel<<<NCTA, NTHR, MLP_SMEM>>>(
        x, budget, emb_id, emb_period, emb_time,
        bf1, bf2, bc1, bc2, bb1, Wb2, bb2, (float*)d_out);
}

// round 10
// speedup vs baseline: 1.0253x; 1.0253x over previous
#include <cuda_runtime.h>
#include <cuda_bf16.h>
#include <cstdint>

#define BATCH 2048
#define RPB   16       // rows per MLP CTA
#define NCTA  128
#define NTHR  512      // 16 warps, each owns an 8-col N-slice
#define XCOLS 39
#define HID   128
#define WP    272      // W/A smem pitch bytes (136 bf16)

// ---- smem byte offsets ----
#define S0H 0
#define S0L 34816
#define S1H 69632
#define S1L 104448
#define E_H 139264     // emb A hi [16][WP]
#define E_L 143616
#define AAH 147968     // actA
#define AAL 152320
#define ABH 156672     // actB
#define ABL 161024
#define OHC 165376     // hc f32 [16][128]
#define OHB 173568     // hb f32 [16][128]
#define OW2 181760     // wc2bar [128][8] f32
#define OB1 185856     // bf1 [128]
#define OB2 186368     // bf2
#define OB3 186880     // bc1
#define OB4 187392     // bb1
#define OWB 187904     // Wb2
#define OBC 188416     // bc2bar[6], [6]=bb2
#define OCB 188448     // cbar sbase [16][8] (only [r][6] used for sbase)
#define OCF 188960     // coefB [16][4][4]
#define ORD 189984     // reduce partials [16][8][4] f32
#define OIX 192032     // x categorical idx [16][3] int + pad
#define MLP_SMEM 192224

// preconverted weights: [m][128][128] bf16, m = {f1(rows>=68 zero), f2, c1, b1}
__device__ __nv_bfloat16 g_whi[4 * 128 * 128];
__device__ __nv_bfloat16 g_wlo[4 * 128 * 128];
__device__ float g_wc2bar[128 * 8];

// ---------------- PTX wrappers ----------------
__device__ __forceinline__ void ldm4(uint32_t r[4], uint32_t a) {
    asm volatile("ldmatrix.sync.aligned.m8n8.x4.shared.b16 {%0,%1,%2,%3}, [%4];"
                 : "=r"(r[0]), "=r"(r[1]), "=r"(r[2]), "=r"(r[3]) : "r"(a));
}
__device__ __forceinline__ void ldm2t(uint32_t r[2], uint32_t a) {
    asm volatile("ldmatrix.sync.aligned.m8n8.x2.trans.shared.b16 {%0,%1}, [%2];"
                 : "=r"(r[0]), "=r"(r[1]) : "r"(a));
}
__device__ __forceinline__ void mma_bf16(float d[4], const uint32_t a[4],
                                         uint32_t b0, uint32_t b1) {
    asm("mma.sync.aligned.m16n8k16.row.col.f32.bf16.bf16.f32 "
        "{%0,%1,%2,%3}, {%4,%5,%6,%7}, {%8,%9}, {%0,%1,%2,%3};"
        : "+f"(d[0]), "+f"(d[1]), "+f"(d[2]), "+f"(d[3])
        : "r"(a[0]), "r"(a[1]), "r"(a[2]), "r"(a[3]), "r"(b0), "r"(b1));
}
__device__ __forceinline__ void split2(float v0, float v1, uint32_t& hi, uint32_t& lo) {
    __nv_bfloat162 h = __floats2bfloat162_rn(v0, v1);
    float f0 = __bfloat162float(h.x), f1 = __bfloat162float(h.y);
    __nv_bfloat162 g = __floats2bfloat162_rn(v0 - f0, v1 - f1);
    hi = *reinterpret_cast<uint32_t*>(&h);
    lo = *reinterpret_cast<uint32_t*>(&g);
}
__device__ __forceinline__ void cp16(uint32_t dst_smem, const void* src) {
    asm volatile("cp.async.cg.shared.global [%0], [%1], 16;\n" :: "r"(dst_smem), "l"(src));
}
#define CP_COMMIT() asm volatile("cp.async.commit_group;\n" ::: "memory")
#define CP_WAIT0()  asm volatile("cp.async.wait_group 0;\n" ::: "memory")
#define CP_WAIT1()  asm volatile("cp.async.wait_group 1;\n" ::: "memory")

// ---------------- weight preconvert kernel ----------------
__global__ __launch_bounds__(256) void convert_kernel(
    const float* __restrict__ Wf1, const float* __restrict__ Wf2,
    const float* __restrict__ Wc1, const float* __restrict__ Wb1,
    const float* __restrict__ Wc2)
{
    int tid = threadIdx.x;
    if (blockIdx.x < 64) {
        int idx = blockIdx.x * 256 + tid;      // 16384 float4 tasks
        int m = idx >> 12, r = idx & 4095;
        int k = r >> 5, n4 = (r & 31) * 4;
        float4 v = make_float4(0.f, 0.f, 0.f, 0.f);
        const float* src = (m == 0) ? Wf1 : (m == 1) ? Wf2 : (m == 2) ? Wc1 : Wb1;
        if (m != 0 || k < 68) v = *(const float4*)(src + k * 128 + n4);
        uint32_t h0, l0, h1, l1;
        split2(v.x, v.y, h0, l0);
        split2(v.z, v.w, h1, l1);
        int e = (m << 14) + k * 128 + n4;
        *(uint2*)((char*)g_whi + e * 2) = make_uint2(h0, h1);
        *(uint2*)((char*)g_wlo + e * 2) = make_uint2(l0, l1);
    } else if (tid < 128) {
        float s[6] = {0, 0, 0, 0, 0, 0};
        const float4* w4 = (const float4*)(Wc2 + tid * 48);
        #pragma unroll
        for (int v = 0; v < 12; v++) {
            float4 f = w4[v];
            s[(v * 4 + 0) % 6] += f.x; s[(v * 4 + 1) % 6] += f.y;
            s[(v * 4 + 2) % 6] += f.z; s[(v * 4 + 3) % 6] += f.w;
        }
        #pragma unroll
        for (int k = 0; k < 6; k++) g_wc2bar[tid * 8 + k] = s[k] * 0.125f;
        g_wc2bar[tid * 8 + 6] = 0.f; g_wc2bar[tid * 8 + 7] = 0.f;
    }
}

// stage preconverted matrix m into smem hi/lo tiles [rows][WP]
__device__ __forceinline__ void stage_pre(int m, char* smem, int offH, int offL,
                                          int rows, int tid)
{
    const char* sH = (const char*)(g_whi + (m << 14));
    const char* sL = (const char*)(g_wlo + (m << 14));
    uint32_t dH = (uint32_t)__cvta_generic_to_shared(smem + offH);
    uint32_t dL = (uint32_t)__cvta_generic_to_shared(smem + offL);
    int tot = rows * 16;
    for (int i = tid; i < tot; i += NTHR) {
        int k = i >> 4, n = (i & 15) * 16;
        cp16(dH + k * WP + n, sH + k * 256 + n);
        cp16(dL + k * WP + n, sL + k * 256 + n);
    }
}

// load A fragments (ks ksteps) from act buffer (broadcast to all warps)
__device__ __forceinline__ void loadA(uint32_t ahi[8][4], uint32_t alo[8][4],
                                      uint32_t bH, uint32_t bL, int ks, int lr, int lc)
{
    uint32_t base = lr * WP + lc * 2;
    for (int K = 0; K < ks; K++) {
        ldm4(ahi[K], bH + base + K * 32);
        ldm4(alo[K], bL + base + K * 32);
    }
}

// warp MMA over its 8-col N slice; 3 INDEPENDENT accumulator chains
// acc[0]: ahi*whi, acc[1]: ahi*wlo, acc[2]: alo*whi; ldm2t pipelined 1 ahead
template<int KS>
__device__ __forceinline__ void mma8(float acc[3][4],
                                     const uint32_t ahi[8][4], const uint32_t alo[8][4],
                                     uint32_t wH, uint32_t wL,
                                     int lr, uint32_t wcolb)
{
    uint32_t base = (uint32_t)(lr * WP) + wcolb;
    uint32_t bh[2], bl[2], bh2[2], bl2[2];
    ldm2t(bh, wH + base);
    ldm2t(bl, wL + base);
    #pragma unroll
    for (int K = 0; K < KS; K++) {
        if (K + 1 < KS) {
            uint32_t ro = base + (uint32_t)((K + 1) * 16 * WP);
            ldm2t(bh2, wH + ro);
            ldm2t(bl2, wL + ro);
        }
        mma_bf16(acc[0], ahi[K], bh[0], bh[1]);
        mma_bf16(acc[1], ahi[K], bl[0], bl[1]);
        mma_bf16(acc[2], alo[K], bh[0], bh[1]);
        bh[0] = bh2[0]; bh[1] = bh2[1];
        bl[0] = bl2[0]; bl[1] = bl2[1];
    }
}

// bias+relu -> bf16 hi/lo act buffer (8-col slice); reset accs
__device__ __forceinline__ void epi_act(float acc[3][4], const float* __restrict__ bias,
                                        char* smem, int offH, int offL,
                                        int w, int lane)
{
    int r0 = lane >> 2, ql = lane & 3;
    int c = w * 8 + 2 * ql;
    float2 b = *(const float2*)(bias + c);
    float v0 = fmaxf(acc[0][0] + acc[1][0] + acc[2][0] + b.x, 0.f);
    float v1 = fmaxf(acc[0][1] + acc[1][1] + acc[2][1] + b.y, 0.f);
    float v2 = fmaxf(acc[0][2] + acc[1][2] + acc[2][2] + b.x, 0.f);
    float v3 = fmaxf(acc[0][3] + acc[1][3] + acc[2][3] + b.y, 0.f);
    uint32_t h0, l0, h1, l1;
    split2(v0, v1, h0, l0);
    split2(v2, v3, h1, l1);
    *(uint32_t*)(smem + offH + r0 * WP + c * 2)       = h0;
    *(uint32_t*)(smem + offL + r0 * WP + c * 2)       = l0;
    *(uint32_t*)(smem + offH + (r0 + 8) * WP + c * 2) = h1;
    *(uint32_t*)(smem + offL + (r0 + 8) * WP + c * 2) = l1;
    #pragma unroll
    for (int p = 0; p < 3; p++)
        acc[p][0] = acc[p][1] = acc[p][2] = acc[p][3] = 0.f;
}

// bias+relu -> f32 buffer [16][128] (8-col slice); reset accs
__device__ __forceinline__ void epi_f32(float acc[3][4], const float* __restrict__ bias,
                                        float* __restrict__ dst, int w, int lane)
{
    int r0 = lane >> 2, ql = lane & 3;
    int c = w * 8 + 2 * ql;
    float2 b = *(const float2*)(bias + c);
    *(float2*)(dst + r0 * 128 + c) =
        make_float2(fmaxf(acc[0][0] + acc[1][0] + acc[2][0] + b.x, 0.f),
                    fmaxf(acc[0][1] + acc[1][1] + acc[2][1] + b.y, 0.f));
    *(float2*)(dst + (r0 + 8) * 128 + c) =
        make_float2(fmaxf(acc[0][2] + acc[1][2] + acc[2][2] + b.x, 0.f),
                    fmaxf(acc[0][3] + acc[1][3] + acc[2][3] + b.y, 0.f));
    #pragma unroll
    for (int p = 0; p < 3; p++)
        acc[p][0] = acc[p][1] = acc[p][2] = acc[p][3] = 0.f;
}

__global__ __launch_bounds__(NTHR, 1) void mlp_kernel(
    const float* __restrict__ x,
    const float* __restrict__ budget,
    const float* __restrict__ emb_id, const float* __restrict__ emb_period,
    const float* __restrict__ emb_time,
    const float* __restrict__ bf1, const float* __restrict__ bf2,
    const float* __restrict__ bc1, const float* __restrict__ bc2,
    const float* __restrict__ bb1, const float* __restrict__ Wb2,
    const float* __restrict__ bb2,
    float* __restrict__ out)
{
    extern __shared__ char smem[];
    float* smf = (float*)smem;
    const int tid  = threadIdx.x;
    const int w    = tid >> 5;
    const int lane = tid & 31;
    const int lr   = lane & 15;
    const int lc   = (lane >> 4) * 8;
    const int row0 = blockIdx.x * RPB;
    const uint32_t smb = (uint32_t)__cvta_generic_to_shared(smem);
    const uint32_t wcolb = (uint32_t)(w * 16);   // byte offset of warp's 8-col slice

    // ---- categorical index prefetch (breaks the emb gather chain) ----
    if (tid < 48) {
        int r = tid / 3, c = tid - r * 3;
        ((int*)(smem + OIX))[r * 3 + c] = (int)x[(row0 + r) * XCOLS + c];
    }

    // ---- budget prefetch: independent of everything; hides behind the MLP ----
    const float4* bud4 = (const float4*)budget + row0 * 128;
    float4 pf[4];
    #pragma unroll
    for (int it = 0; it < 4; it++) pf[it] = bud4[tid + it * NTHR];

    // zero E hi/lo (covers zero-pad cols 68..79); 544 uint4
    for (int i = tid; i < 544; i += NTHR)
        ((uint4*)(smem + E_H))[i] = make_uint4(0, 0, 0, 0);

    // stage f1 (80 rows incl. zero rows) -> S0, f2 -> S1
    stage_pre(0, smem, S0H, S0L, 80, tid);  CP_COMMIT();
    stage_pre(1, smem, S1H, S1L, 128, tid); CP_COMMIT();

    // wc2bar copy, biases
    if (tid < 256)
        ((float4*)(smem + OW2))[tid] = ((const float4*)g_wc2bar)[tid];
    else if (tid < 384) {
        int t = tid - 256;
        smf[OB1 / 4 + t] = bf1[t];
        smf[OB2 / 4 + t] = bf2[t];
        smf[OB3 / 4 + t] = bc1[t];
        smf[OB4 / 4 + t] = bb1[t];
        smf[OWB / 4 + t] = Wb2[t];
    } else if (tid < 390) {
        int t = tid - 384;
        float s = 0.f;
        #pragma unroll
        for (int j = 0; j < 8; j++) s += bc2[j * 6 + t];
        smf[OBC / 4 + t] = s * 0.125f;
    } else if (tid == 390) {
        smf[OBC / 4 + 6] = bb2[0];
    }
    __syncthreads();   // E zeros + indices visible

    // emb fill: 16 rows x 68 cols, bf16 hi/lo (1-hop gathers via smem idx)
    {
        const int* ix = (const int*)(smem + OIX);
        for (int idx = tid; idx < RPB * 68; idx += NTHR) {
            int r = idx / 68, c = idx % 68;
            float v;
            if      (c < 8)  v = emb_id    [ix[r * 3 + 1] * 8  + c];
            else if (c < 16) v = emb_period[ix[r * 3 + 0] * 8  + (c - 8)];
            else if (c < 32) v = emb_time  [ix[r * 3 + 2] * 16 + (c - 16)];
            else             v = x[(row0 + r) * XCOLS + 3 + (c - 32)];
            __nv_bfloat16 h = __float2bfloat16(v);
            __nv_bfloat16 l = __float2bfloat16(v - __bfloat162float(h));
            *(__nv_bfloat16*)(smem + E_H + r * WP + c * 2) = h;
            *(__nv_bfloat16*)(smem + E_L + r * WP + c * 2) = l;
        }
    }
    CP_WAIT1();        // f1 arrived
    __syncthreads();   // emb visible

    float acc[3][4];
    #pragma unroll
    for (int p = 0; p < 3; p++)
        acc[p][0] = acc[p][1] = acc[p][2] = acc[p][3] = 0.f;
    uint32_t ahi[8][4], alo[8][4];

    // ---- L1: E x Wf1(S0) -> actA ----
    loadA(ahi, alo, smb + E_H, smb + E_L, 5, lr, lc);
    mma8<5>(acc, ahi, alo, smb + S0H, smb + S0L, lr, wcolb);
    epi_act(acc, smf + OB1 / 4, smem, AAH, AAL, w, lane);
    CP_WAIT0();        // f2 arrived
    __syncthreads();   // actA visible, S0 free

    // ---- L2: actA x Wf2(S1) -> actB;  prefetch c1 -> S0 ----
    stage_pre(2, smem, S0H, S0L, 128, tid); CP_COMMIT();
    loadA(ahi, alo, smb + AAH, smb + AAL, 8, lr, lc);
    mma8<8>(acc, ahi, alo, smb + S1H, smb + S1L, lr, wcolb);
    epi_act(acc, smf + OB2 / 4, smem, ABH, ABL, w, lane);
    __syncthreads();   // actB visible, S1 free

    // ---- prefetch b1 -> S1; L3: actB x Wc1(S0) -> hc ----
    stage_pre(3, smem, S1H, S1L, 128, tid); CP_COMMIT();
    CP_WAIT1();        // c1 arrived
    loadA(ahi, alo, smb + ABH, smb + ABL, 8, lr, lc);
    mma8<8>(acc, ahi, alo, smb + S0H, smb + S0L, lr, wcolb);
    epi_f32(acc, smf + OB3 / 4, smf + OHC / 4, w, lane);

    // ---- L4: actB x Wb1(S1) -> hb (same A frags) ----
    CP_WAIT0();        // b1 arrived
    mma8<8>(acc, ahi, alo, smb + S1H, smb + S1L, lr, wcolb);
    epi_f32(acc, smf + OB4 / 4, smf + OHB / 4, w, lane);
    __syncthreads();

    // ---- partial dots: (rb 16) x (slot 8) x (quarter 4) ----
    {
        int rb = tid >> 5, rem = tid & 31;
        int slot = rem >> 2, q = rem & 3;
        float s = 0.f;
        if (slot < 6) {
            const float* hc = smf + OHC / 4 + rb * 128 + q * 32;
            const float* wz = smf + OW2 / 4 + q * 32 * 8 + slot;
            #pragma unroll 8
            for (int i = 0; i < 32; i++) s += hc[i] * wz[i * 8];
        } else if (slot == 6) {
            const float* hb = smf + OHB / 4 + rb * 128 + q * 32;
            const float* wb = smf + OWB / 4 + q * 32;
            #pragma unroll 8
            for (int i = 0; i < 32; i++) s += hb[i] * wb[i];
        }
        smf[ORD / 4 + (rb * 8 + slot) * 4 + q] = s;
    }
    __syncthreads();

    // ---- fused combine + cubic: 48 cubic tasks + 16 sbase tasks ----
    if (tid < 48) {
        int rb = tid / 3, m = tid - rb * 3;
        float cb[4];
        #pragma unroll
        for (int j = 0; j < 4; j++) {
            const float* r = smf + ORD / 4 + (rb * 8 + (m + j)) * 4;
            cb[j] = r[0] + r[1] + r[2] + r[3] + smf[OBC / 4 + (m + j)];
        }
        float c0 = cb[0], c1 = cb[1], c2 = cb[2], c3 = cb[3];
        const float k6 = 1.f / 6.f;
        float A0 = (c0 + 4.f * c1 + c2) * k6;
        float A1 = (c2 - c0) * 0.5f;
        float A2 = (c0 - 2.f * c1 + c2) * 0.5f;
        float A3 = (c3 - c0 + 3.f * (c1 - c2)) * k6;
        float d  = 1.5f - (float)m;
        float B0 = A0 + d * (A1 + d * (A2 + d * A3));
        float B1 = 1.5f * (A1 + d * (2.f * A2 + 3.f * A3 * d));
        float B2 = 2.25f * (A2 + 3.f * A3 * d);
        float B3 = 3.375f * A3;
        ((float4*)(smem + OCF))[rb * 4 + m] = make_float4(B0, B1, B2, B3);
    } else if (tid < 64) {
        int rb = tid - 48;
        const float* r = smf + ORD / 4 + (rb * 8 + 6) * 4;
        smf[OCB / 4 + rb * 8 + 6] = r[0] + r[1] + r[2] + r[3] + smf[OBC / 4 + 6];
    }
    __syncthreads();

    // ---- budget phase: data already in pf[] registers ----
    float4* out4 = (float4*)out + row0 * 128;
    const float4* cb4 = (const float4*)(smem + OCF);
    #pragma unroll
    for (int it = 0; it < 4; it++) {
        int q = tid + it * NTHR;
        int row = q >> 7;
        float4 bv = pf[it];
        float sb = smf[OCB / 4 + row * 8 + 6];
        float xs[4] = {bv.x, bv.y, bv.z, bv.w};
        float o[4];
        #pragma unroll
        for (int e = 0; e < 4; e++) {
            float X = xs[e];
            float tp = fmaf(X, 1.5f, 1.5f);
            int m = min((int)tp, 2);
            float4 B = cb4[row * 4 + m];
            float sp = fmaf(fmaf(fmaf(B.w, X, B.z), X, B.y), X, B.x);
            float u = X * X;
            float P = fmaf(u, fmaf(u, fmaf(u, fmaf(u, 2.1357286e-5f, -2.1081349e-4f),
                                           2.0833333e-3f), -2.0833333e-2f), 0.25f);
            float sil = X * fmaf(X, P, 0.5f);
            o[e] = sb * (sil + sp);
        }
        out4[q] = make_float4(o[0], o[1], o[2], o[3]);
    }
}

extern "C" void kernel_launch(void* const* d_in, const int* in_sizes, int n_in,
                              void* d_out, int out_size)
{
    const float* x          = (const float*)d_in[0];
    const float* budget     = (const float*)d_in[1];
    const float* emb_id     = (const float*)d_in[2];
    const float* emb_period = (const float*)d_in[3];
    const float* emb_time   = (const float*)d_in[4];
    const float* Wf1 = (const float*)d_in[5];
    const float* bf1 = (const float*)d_in[6];
    const float* Wf2 = (const float*)d_in[7];
    const float* bf2 = (const float*)d_in[8];
    const float* Wc1 = (const float*)d_in[9];
    const float* bc1 = (const float*)d_in[10];
    const float* Wc2 = (const float*)d_in[11];
    const float* bc2 = (const float*)d_in[12];
    // d_in[13..16] = Ws1/bs1/Ws2/bs2 : unused in reference output
    const float* Wb1 = (const float*)d_in[17];
    const float* bb1 = (const float*)d_in[18];
    const float* Wb2 = (const float*)d_in[19];
    const float* bb2 = (const float*)d_in[20];

    cudaFuncSetAttribute(mlp_kernel, cudaFuncAttributeMaxDynamicSharedMemorySize, MLP_SMEM);

    convert_kernel<<<65, 256>>>(Wf1, Wf2, Wc1, Wb1, Wc2);
    mlp_kernel<<<NCTA, NTHR, MLP_SMEM>>>(
        x, budget, emb_id, emb_period, emb_time,
        bf1, bf2, bc1, bc2, bb1, Wb2, bb2, (float*)d_out);
}

// round 11
// speedup vs baseline: 1.1712x; 1.1423x over previous
#include <cuda_runtime.h>
#include <cuda_bf16.h>
#include <cstdint>

#define BATCH 2048
#define RPB   16       // rows per MLP CTA
#define NCTA  128
#define NTHR  512      // 16 warps, each owns an 8-col N-slice
#define XCOLS 39
#define HID   128
#define WP    272      // W/A smem pitch bytes (136 bf16)

// ---- smem byte offsets ----
#define S0H 0
#define S0L 34816
#define S1H 69632
#define S1L 104448
#define E_H 139264     // emb A hi [16][WP]
#define E_L 143616
#define AAH 147968     // actA
#define AAL 152320
#define ABH 156672     // actB
#define ABL 161024
#define OW2 165376     // wc2bar [128][8] f32  (4096)
#define OB1 169472     // bf1 [128]
#define OB2 169984     // bf2
#define OB3 170496     // bc1
#define OB4 171008     // bb1
#define OWB 171520     // Wb2
#define OBC 172032     // bc2bar[6], [6]=bb2 (32B)
#define OSB 172064     // sbase [16] (64B)
#define OCF 172128     // coefB [16][4][4] (256B)
#define OPC 172384     // cbar partials [16w][16row][6] (6144B)
#define OPB 178528     // sbase partials [16w][16row] (1024B)
#define OIX 179552     // x categorical idx [16][3] int (192B)
#define MLP_SMEM 179744

// preconverted weights: [m][128][128] bf16, m = {f1(rows>=68 zero), f2, c1, b1}
__device__ __nv_bfloat16 g_whi[4 * 128 * 128];
__device__ __nv_bfloat16 g_wlo[4 * 128 * 128];
__device__ float g_wc2bar[128 * 8];

// ---------------- PTX wrappers ----------------
__device__ __forceinline__ void ldm4(uint32_t r[4], uint32_t a) {
    asm volatile("ldmatrix.sync.aligned.m8n8.x4.shared.b16 {%0,%1,%2,%3}, [%4];"
                 : "=r"(r[0]), "=r"(r[1]), "=r"(r[2]), "=r"(r[3]) : "r"(a));
}
__device__ __forceinline__ void ldm2t(uint32_t r[2], uint32_t a) {
    asm volatile("ldmatrix.sync.aligned.m8n8.x2.trans.shared.b16 {%0,%1}, [%2];"
                 : "=r"(r[0]), "=r"(r[1]) : "r"(a));
}
__device__ __forceinline__ void mma_bf16(float d[4], const uint32_t a[4],
                                         uint32_t b0, uint32_t b1) {
    asm("mma.sync.aligned.m16n8k16.row.col.f32.bf16.bf16.f32 "
        "{%0,%1,%2,%3}, {%4,%5,%6,%7}, {%8,%9}, {%0,%1,%2,%3};"
        : "+f"(d[0]), "+f"(d[1]), "+f"(d[2]), "+f"(d[3])
        : "r"(a[0]), "r"(a[1]), "r"(a[2]), "r"(a[3]), "r"(b0), "r"(b1));
}
__device__ __forceinline__ void split2(float v0, float v1, uint32_t& hi, uint32_t& lo) {
    __nv_bfloat162 h = __floats2bfloat162_rn(v0, v1);
    float f0 = __bfloat162float(h.x), f1 = __bfloat162float(h.y);
    __nv_bfloat162 g = __floats2bfloat162_rn(v0 - f0, v1 - f1);
    hi = *reinterpret_cast<uint32_t*>(&h);
    lo = *reinterpret_cast<uint32_t*>(&g);
}
__device__ __forceinline__ void cp16(uint32_t dst_smem, const void* src) {
    asm volatile("cp.async.cg.shared.global [%0], [%1], 16;\n" :: "r"(dst_smem), "l"(src));
}
#define CP_COMMIT() asm volatile("cp.async.commit_group;\n" ::: "memory")
#define CP_WAIT0()  asm volatile("cp.async.wait_group 0;\n" ::: "memory")
#define CP_WAIT1()  asm volatile("cp.async.wait_group 1;\n" ::: "memory")

// ---------------- weight preconvert kernel ----------------
__global__ __launch_bounds__(256) void convert_kernel(
    const float* __restrict__ Wf1, const float* __restrict__ Wf2,
    const float* __restrict__ Wc1, const float* __restrict__ Wb1,
    const float* __restrict__ Wc2)
{
    int tid = threadIdx.x;
    if (blockIdx.x < 64) {
        int idx = blockIdx.x * 256 + tid;      // 16384 float4 tasks
        int m = idx >> 12, r = idx & 4095;
        int k = r >> 5, n4 = (r & 31) * 4;
        float4 v = make_float4(0.f, 0.f, 0.f, 0.f);
        const float* src = (m == 0) ? Wf1 : (m == 1) ? Wf2 : (m == 2) ? Wc1 : Wb1;
        if (m != 0 || k < 68) v = *(const float4*)(src + k * 128 + n4);
        uint32_t h0, l0, h1, l1;
        split2(v.x, v.y, h0, l0);
        split2(v.z, v.w, h1, l1);
        int e = (m << 14) + k * 128 + n4;
        *(uint2*)((char*)g_whi + e * 2) = make_uint2(h0, h1);
        *(uint2*)((char*)g_wlo + e * 2) = make_uint2(l0, l1);
    } else if (tid < 128) {
        float s[6] = {0, 0, 0, 0, 0, 0};
        const float4* w4 = (const float4*)(Wc2 + tid * 48);
        #pragma unroll
        for (int v = 0; v < 12; v++) {
            float4 f = w4[v];
            s[(v * 4 + 0) % 6] += f.x; s[(v * 4 + 1) % 6] += f.y;
            s[(v * 4 + 2) % 6] += f.z; s[(v * 4 + 3) % 6] += f.w;
        }
        #pragma unroll
        for (int k = 0; k < 6; k++) g_wc2bar[tid * 8 + k] = s[k] * 0.125f;
        g_wc2bar[tid * 8 + 6] = 0.f; g_wc2bar[tid * 8 + 7] = 0.f;
    }
}

// stage preconverted matrix m into smem hi/lo tiles [ROWS][WP]; unrolled,
// strength-reduced addressing (i = tid + j*512 -> k = (tid>>4)+32j, n = (tid&15)*16)
template<int ROWS>
__device__ __forceinline__ void stage_pre(int m, char* smem, int offH, int offL, int tid)
{
    const char* sH = (const char*)(g_whi + (m << 14));
    const char* sL = (const char*)(g_wlo + (m << 14));
    uint32_t dH = (uint32_t)__cvta_generic_to_shared(smem + offH);
    uint32_t dL = (uint32_t)__cvta_generic_to_shared(smem + offL);
    int k0 = tid >> 4, n = (tid & 15) * 16;
    uint32_t d0 = (uint32_t)(k0 * WP + n);
    int s0 = k0 * 256 + n;
    constexpr int TOT = ROWS * 16;
    #pragma unroll
    for (int j = 0; j < TOT / 512; j++) {
        cp16(dH + d0 + j * (32 * WP), sH + s0 + j * 8192);
        cp16(dL + d0 + j * (32 * WP), sL + s0 + j * 8192);
    }
    if constexpr (TOT % 512 != 0) {
        if (tid < TOT % 512) {
            constexpr int J = TOT / 512;
            cp16(dH + d0 + J * (32 * WP), sH + s0 + J * 8192);
            cp16(dL + d0 + J * (32 * WP), sL + s0 + J * 8192);
        }
    }
}

// load A fragments from act buffer (broadcast to all warps)
template<int KS>
__device__ __forceinline__ void loadA(uint32_t ahi[8][4], uint32_t alo[8][4],
                                      uint32_t bH, uint32_t bL, int lr, int lc)
{
    uint32_t base = lr * WP + lc * 2;
    #pragma unroll
    for (int K = 0; K < KS; K++) {
        ldm4(ahi[K], bH + base + K * 32);
        ldm4(alo[K], bL + base + K * 32);
    }
}

// warp MMA over its 8-col N slice; 3 independent accumulator chains
template<int KS>
__device__ __forceinline__ void mma8(float acc[3][4],
                                     const uint32_t ahi[8][4], const uint32_t alo[8][4],
                                     uint32_t wH, uint32_t wL,
                                     int lr, uint32_t wcolb)
{
    uint32_t base = (uint32_t)(lr * WP) + wcolb;
    uint32_t bh[2], bl[2], bh2[2], bl2[2];
    ldm2t(bh, wH + base);
    ldm2t(bl, wL + base);
    #pragma unroll
    for (int K = 0; K < KS; K++) {
        if (K + 1 < KS) {
            uint32_t ro = base + (uint32_t)((K + 1) * 16 * WP);
            ldm2t(bh2, wH + ro);
            ldm2t(bl2, wL + ro);
        }
        mma_bf16(acc[0], ahi[K], bh[0], bh[1]);
        mma_bf16(acc[1], ahi[K], bl[0], bl[1]);
        mma_bf16(acc[2], alo[K], bh[0], bh[1]);
        bh[0] = bh2[0]; bh[1] = bh2[1];
        bl[0] = bl2[0]; bl[1] = bl2[1];
    }
}

// bias+relu -> bf16 hi/lo act buffer (8-col slice); reset accs
__device__ __forceinline__ void epi_act(float acc[3][4], const float* __restrict__ bias,
                                        char* smem, int offH, int offL,
                                        int w, int lane)
{
    int r0 = lane >> 2, ql = lane & 3;
    int c = w * 8 + 2 * ql;
    float2 b = *(const float2*)(bias + c);
    float v0 = fmaxf(acc[0][0] + acc[1][0] + acc[2][0] + b.x, 0.f);
    float v1 = fmaxf(acc[0][1] + acc[1][1] + acc[2][1] + b.y, 0.f);
    float v2 = fmaxf(acc[0][2] + acc[1][2] + acc[2][2] + b.x, 0.f);
    float v3 = fmaxf(acc[0][3] + acc[1][3] + acc[2][3] + b.y, 0.f);
    uint32_t h0, l0, h1, l1;
    split2(v0, v1, h0, l0);
    split2(v2, v3, h1, l1);
    *(uint32_t*)(smem + offH + r0 * WP + c * 2)       = h0;
    *(uint32_t*)(smem + offL + r0 * WP + c * 2)       = l0;
    *(uint32_t*)(smem + offH + (r0 + 8) * WP + c * 2) = h1;
    *(uint32_t*)(smem + offL + (r0 + 8) * WP + c * 2) = l1;
    #pragma unroll
    for (int p = 0; p < 3; p++)
        acc[p][0] = acc[p][1] = acc[p][2] = acc[p][3] = 0.f;
}

__global__ __launch_bounds__(NTHR, 1) void mlp_kernel(
    const float* __restrict__ x,
    const float* __restrict__ budget,
    const float* __restrict__ emb_id, const float* __restrict__ emb_period,
    const float* __restrict__ emb_time,
    const float* __restrict__ bf1, const float* __restrict__ bf2,
    const float* __restrict__ bc1, const float* __restrict__ bc2,
    const float* __restrict__ bb1, const float* __restrict__ Wb2,
    const float* __restrict__ bb2,
    float* __restrict__ out)
{
    extern __shared__ char smem[];
    float* smf = (float*)smem;
    const int tid  = threadIdx.x;
    const int w    = tid >> 5;
    const int lane = tid & 31;
    const int lr   = lane & 15;
    const int lc   = (lane >> 4) * 8;
    const int r0l  = lane >> 2;        // C-fragment row within tile
    const int ql   = lane & 3;         // quad lane
    const int row0 = blockIdx.x * RPB;
    const uint32_t smb = (uint32_t)__cvta_generic_to_shared(smem);
    const uint32_t wcolb = (uint32_t)(w * 16);   // byte offset of warp's 8-col slice

    // ======== PDL-independent prologue (runs while convert_kernel finishes) ====
    if (tid < 48) {
        int r = tid / 3, c = tid - r * 3;
        ((int*)(smem + OIX))[r * 3 + c] = (int)x[(row0 + r) * XCOLS + c];
    }
    // budget prefetch -> registers (hides behind the MLP)
    const float4* bud4 = (const float4*)budget + row0 * 128;
    float4 pf[4];
    #pragma unroll
    for (int it = 0; it < 4; it++) pf[it] = bud4[tid + it * NTHR];

    // zero E hi/lo (covers zero-pad cols 68..79); 544 uint4
    for (int i = tid; i < 544; i += NTHR)
        ((uint4*)(smem + E_H))[i] = make_uint4(0, 0, 0, 0);

    // biases (harness inputs, independent of convert)
    if (tid < 128) {
        smf[OB1 / 4 + tid] = bf1[tid];
        smf[OB2 / 4 + tid] = bf2[tid];
        smf[OB3 / 4 + tid] = bc1[tid];
        smf[OB4 / 4 + tid] = bb1[tid];
        smf[OWB / 4 + tid] = Wb2[tid];
    } else if (tid < 134) {
        int t = tid - 128;
        float s = 0.f;
        #pragma unroll
        for (int j = 0; j < 8; j++) s += bc2[j * 6 + t];
        smf[OBC / 4 + t] = s * 0.125f;
    } else if (tid == 134) {
        smf[OBC / 4 + 6] = bb2[0];
    }
    __syncthreads();   // E zeros + indices visible

    // emb fill: row = tid>>5, cols lane, lane+32, lane+64 (div-free)
    {
        const int* ix = (const int*)(smem + OIX);
        int r = tid >> 5;
        int i0 = ix[r * 3 + 0], i1 = ix[r * 3 + 1], i2 = ix[r * 3 + 2];
        #pragma unroll
        for (int jj = 0; jj < 3; jj++) {
            int c = lane + jj * 32;
            if (c < 68) {
                float v;
                if      (c < 8)  v = emb_id    [i1 * 8  + c];
                else if (c < 16) v = emb_period[i0 * 8  + (c - 8)];
                else if (c < 32) v = emb_time  [i2 * 16 + (c - 16)];
                else             v = x[(row0 + r) * XCOLS + 3 + (c - 32)];
                __nv_bfloat16 h = __float2bfloat16(v);
                __nv_bfloat16 l = __float2bfloat16(v - __bfloat162float(h));
                *(__nv_bfloat16*)(smem + E_H + r * WP + c * 2) = h;
                *(__nv_bfloat16*)(smem + E_L + r * WP + c * 2) = l;
            }
        }
    }

    // ======== wait for convert_kernel's weights, then stage ========
    cudaGridDependencySynchronize();

    stage_pre<80>(0, smem, S0H, S0L, tid);  CP_COMMIT();
    stage_pre<128>(1, smem, S1H, S1L, tid); CP_COMMIT();
    if (tid < 256)
        ((float4*)(smem + OW2))[tid] = ((const float4*)g_wc2bar)[tid];
    CP_WAIT1();        // f1 arrived (this thread)
    __syncthreads();   // all threads' f1 copies + emb visible

    float acc[3][4];
    #pragma unroll
    for (int p = 0; p < 3; p++)
        acc[p][0] = acc[p][1] = acc[p][2] = acc[p][3] = 0.f;
    uint32_t ahi[8][4], alo[8][4];

    // ---- L1: E x Wf1(S0) -> actA ----
    loadA<5>(ahi, alo, smb + E_H, smb + E_L, lr, lc);
    mma8<5>(acc, ahi, alo, smb + S0H, smb + S0L, lr, wcolb);
    epi_act(acc, smf + OB1 / 4, smem, AAH, AAL, w, lane);
    CP_WAIT0();        // f2 arrived
    __syncthreads();   // actA + f2 visible, S0 free

    // ---- L2: actA x Wf2(S1) -> actB;  prefetch c1 -> S0 ----
    stage_pre<128>(2, smem, S0H, S0L, tid); CP_COMMIT();
    loadA<8>(ahi, alo, smb + AAH, smb + AAL, lr, lc);
    mma8<8>(acc, ahi, alo, smb + S1H, smb + S1L, lr, wcolb);
    epi_act(acc, smf + OB2 / 4, smem, ABH, ABL, w, lane);
    CP_WAIT0();        // c1 arrived
    __syncthreads();   // actB + c1 visible, S1 free

    // ---- L3: actB x Wc1(S0) -> cbar partials (fragment-direct);  prefetch b1 -> S1 ----
    stage_pre<128>(3, smem, S1H, S1L, tid); CP_COMMIT();
    loadA<8>(ahi, alo, smb + ABH, smb + ABL, lr, lc);
    mma8<8>(acc, ahi, alo, smb + S0H, smb + S0L, lr, wcolb);
    {
        int c0 = w * 8 + 2 * ql;
        float2 b = *(const float2*)(smf + OB3 / 4 + c0);
        float v00 = fmaxf(acc[0][0] + acc[1][0] + acc[2][0] + b.x, 0.f);
        float v01 = fmaxf(acc[0][1] + acc[1][1] + acc[2][1] + b.y, 0.f);
        float v10 = fmaxf(acc[0][2] + acc[1][2] + acc[2][2] + b.x, 0.f);
        float v11 = fmaxf(acc[0][3] + acc[1][3] + acc[2][3] + b.y, 0.f);
        const float* w0p = smf + OW2 / 4 + c0 * 8;
        const float* w1p = w0p + 8;
        float p0[6], p1[6];
        #pragma unroll
        for (int k = 0; k < 6; k++) {
            p0[k] = v00 * w0p[k] + v01 * w1p[k];
            p1[k] = v10 * w0p[k] + v11 * w1p[k];
        }
        #pragma unroll
        for (int k = 0; k < 6; k++) {
            p0[k] += __shfl_xor_sync(0xffffffff, p0[k], 1);
            p0[k] += __shfl_xor_sync(0xffffffff, p0[k], 2);
            p1[k] += __shfl_xor_sync(0xffffffff, p1[k], 1);
            p1[k] += __shfl_xor_sync(0xffffffff, p1[k], 2);
        }
        if (ql == 0) {
            float* d0 = smf + OPC / 4 + (w * 16 + r0l) * 6;
            float* d1 = smf + OPC / 4 + (w * 16 + r0l + 8) * 6;
            #pragma unroll
            for (int k = 0; k < 6; k++) { d0[k] = p0[k]; d1[k] = p1[k]; }
        }
        #pragma unroll
        for (int p = 0; p < 3; p++)
            acc[p][0] = acc[p][1] = acc[p][2] = acc[p][3] = 0.f;
    }
    CP_WAIT0();        // b1 arrived
    __syncthreads();   // b1 + OPC visible

    // ---- L4: actB x Wb1(S1) -> sbase partials (same A frags) ----
    mma8<8>(acc, ahi, alo, smb + S1H, smb + S1L, lr, wcolb);
    {
        int c0 = w * 8 + 2 * ql;
        float2 b  = *(const float2*)(smf + OB4 / 4 + c0);
        float2 wv = *(const float2*)(smf + OWB / 4 + c0);
        float s0 = fmaxf(acc[0][0] + acc[1][0] + acc[2][0] + b.x, 0.f) * wv.x
                 + fmaxf(acc[0][1] + acc[1][1] + acc[2][1] + b.y, 0.f) * wv.y;
        float s1 = fmaxf(acc[0][2] + acc[1][2] + acc[2][2] + b.x, 0.f) * wv.x
                 + fmaxf(acc[0][3] + acc[1][3] + acc[2][3] + b.y, 0.f) * wv.y;
        s0 += __shfl_xor_sync(0xffffffff, s0, 1);
        s0 += __shfl_xor_sync(0xffffffff, s0, 2);
        s1 += __shfl_xor_sync(0xffffffff, s1, 1);
        s1 += __shfl_xor_sync(0xffffffff, s1, 2);
        if (ql == 0) {
            smf[OPB / 4 + w * 16 + r0l]     = s0;
            smf[OPB / 4 + w * 16 + r0l + 8] = s1;
        }
    }
    __syncthreads();   // OPB visible

    // ---- fused combine + cubic (48 threads) + sbase combine (16 threads) ----
    if (tid < 48) {
        int rb = tid / 3, m = tid - rb * 3;
        float cb[4];
        #pragma unroll
        for (int j = 0; j < 4; j++) {
            float s = smf[OBC / 4 + m + j];
            #pragma unroll
            for (int ww = 0; ww < 16; ww++)
                s += smf[OPC / 4 + (ww * 16 + rb) * 6 + m + j];
            cb[j] = s;
        }
        float c0 = cb[0], c1 = cb[1], c2 = cb[2], c3 = cb[3];
        const float k6 = 1.f / 6.f;
        float A0 = (c0 + 4.f * c1 + c2) * k6;
        float A1 = (c2 - c0) * 0.5f;
        float A2 = (c0 - 2.f * c1 + c2) * 0.5f;
        float A3 = (c3 - c0 + 3.f * (c1 - c2)) * k6;
        float d  = 1.5f - (float)m;
        float B0 = A0 + d * (A1 + d * (A2 + d * A3));
        float B1 = 1.5f * (A1 + d * (2.f * A2 + 3.f * A3 * d));
        float B2 = 2.25f * (A2 + 3.f * A3 * d);
        float B3 = 3.375f * A3;
        ((float4*)(smem + OCF))[rb * 4 + m] = make_float4(B0, B1, B2, B3);
    } else if (tid < 64) {
        int rb = tid - 48;
        float s = smf[OBC / 4 + 6];
        #pragma unroll
        for (int ww = 0; ww < 16; ww++)
            s += smf[OPB / 4 + ww * 16 + rb];
        smf[OSB / 4 + rb] = s;
    }
    __syncthreads();

    // ---- budget phase: data already in pf[] registers ----
    float4* out4 = (float4*)out + row0 * 128;
    const float4* cb4 = (const float4*)(smem + OCF);
    #pragma unroll
    for (int it = 0; it < 4; it++) {
        int q = tid + it * NTHR;
        int row = q >> 7;
        float4 bv = pf[it];
        float sb = smf[OSB / 4 + row];
        float xs[4] = {bv.x, bv.y, bv.z, bv.w};
        float o[4];
        #pragma unroll
        for (int e = 0; e < 4; e++) {
            float X = xs[e];
            float tp = fmaf(X, 1.5f, 1.5f);
            int m = min((int)tp, 2);
            float4 B = cb4[row * 4 + m];
            float sp = fmaf(fmaf(fmaf(B.w, X, B.z), X, B.y), X, B.x);
            float u = X * X;
            float P = fmaf(u, fmaf(u, fmaf(u, fmaf(u, 2.1357286e-5f, -2.1081349e-4f),
                                           2.0833333e-3f), -2.0833333e-2f), 0.25f);
            float sil = X * fmaf(X, P, 0.5f);
            o[e] = sb * (sil + sp);
        }
        out4[q] = make_float4(o[0], o[1], o[2], o[3]);
    }
}

extern "C" void kernel_launch(void* const* d_in, const int* in_sizes, int n_in,
                              void* d_out, int out_size)
{
    const float* x          = (const float*)d_in[0];
    const float* budget     = (const float*)d_in[1];
    const float* emb_id     = (const float*)d_in[2];
    const float* emb_period = (const float*)d_in[3];
    const float* emb_time   = (const float*)d_in[4];
    const float* Wf1 = (const float*)d_in[5];
    const float* bf1 = (const float*)d_in[6];
    const float* Wf2 = (const float*)d_in[7];
    const float* bf2 = (const float*)d_in[8];
    const float* Wc1 = (const float*)d_in[9];
    const float* bc1 = (const float*)d_in[10];
    const float* Wc2 = (const float*)d_in[11];
    const float* bc2 = (const float*)d_in[12];
    // d_in[13..16] = Ws1/bs1/Ws2/bs2 : unused in reference output
    const float* Wb1 = (const float*)d_in[17];
    const float* bb1 = (const float*)d_in[18];
    const float* Wb2 = (const float*)d_in[19];
    const float* bb2 = (const float*)d_in[20];

    cudaFuncSetAttribute(mlp_kernel, cudaFuncAttributeMaxDynamicSharedMemorySize, MLP_SMEM);

    convert_kernel<<<65, 256>>>(Wf1, Wf2, Wc1, Wb1, Wc2);

    // PDL launch: mlp starts while convert drains; prologue runs pre-sync
    cudaLaunchConfig_t cfg = {};
    cfg.gridDim = dim3(NCTA);
    cfg.blockDim = dim3(NTHR);
    cfg.dynamicSmemBytes = MLP_SMEM;
    cfg.stream = 0;
    cudaLaunchAttribute attrs[1];
    attrs[0].id = cudaLaunchAttributeProgrammaticStreamSerialization;
    attrs[0].val.programmaticStreamSerializationAllowed = 1;
    cfg.attrs = attrs;
    cfg.numAttrs = 1;
    cudaLaunchKernelEx(&cfg, mlp_kernel,
                       x, budget, emb_id, emb_period, emb_time,
                       bf1, bf2, bc1, bc2, bb1, Wb2, bb2, (float*)d_out);
}

// round 12
// speedup vs baseline: 1.3594x; 1.1607x over previous
#include <cuda_runtime.h>
#include <cuda_bf16.h>
#include <cstdint>

#define BATCH 2048
#define RPB   16       // rows per MLP CTA
#define NCTA  128
#define NTHR  512      // 16 warps, each owns an 8-col N-slice
#define XCOLS 39
#define HID   128
#define WP    272      // act smem pitch bytes (136 bf16)

// ---- smem byte offsets ----
#define E_H 0          // emb A hi [16][WP]
#define E_L 4352
#define AAH 8704       // actA
#define AAL 13056
#define ABH 17408      // actB
#define ABL 21760
#define OW2 26112      // wc2bar [128][8] f32 (4096)
#define OB1 30208      // bf1 [128]
#define OB2 30720      // bf2
#define OB3 31232      // bc1
#define OB4 31744      // bb1
#define OWB 32256      // Wb2
#define OBC 32768      // bc2bar[6], [6]=bb2 (32B)
#define OSB 32800      // sbase [16] (64B)
#define OCF 32864      // coefB [16][4][4] (256B)
#define OPC 33120      // cbar partials [16w][16row][6] (6144B)
#define OPB 39264      // sbase partials [16w][16row] (1024B)
#define OIX 40288      // x categorical idx [16][3] int (192B)
#define MLP_SMEM 40480

// weights preconverted into mma.sync B-fragment order:
// idx = ((m*8 + K)*16 + slice)*32 + lane ; uint4 = {bh0, bh1, bl0, bl1}
__device__ uint4 g_bfrag[4 * 8 * 16 * 32];
__device__ float g_wc2bar[128 * 8];

// ---------------- PTX wrappers ----------------
__device__ __forceinline__ void ldm4(uint32_t r[4], uint32_t a) {
    asm volatile("ldmatrix.sync.aligned.m8n8.x4.shared.b16 {%0,%1,%2,%3}, [%4];"
                 : "=r"(r[0]), "=r"(r[1]), "=r"(r[2]), "=r"(r[3]) : "r"(a));
}
__device__ __forceinline__ void mma_bf16(float d[4], const uint32_t a[4],
                                         uint32_t b0, uint32_t b1) {
    asm("mma.sync.aligned.m16n8k16.row.col.f32.bf16.bf16.f32 "
        "{%0,%1,%2,%3}, {%4,%5,%6,%7}, {%8,%9}, {%0,%1,%2,%3};"
        : "+f"(d[0]), "+f"(d[1]), "+f"(d[2]), "+f"(d[3])
        : "r"(a[0]), "r"(a[1]), "r"(a[2]), "r"(a[3]), "r"(b0), "r"(b1));
}
__device__ __forceinline__ void split2(float v0, float v1, uint32_t& hi, uint32_t& lo) {
    __nv_bfloat162 h = __floats2bfloat162_rn(v0, v1);
    float f0 = __bfloat162float(h.x), f1 = __bfloat162float(h.y);
    __nv_bfloat162 g = __floats2bfloat162_rn(v0 - f0, v1 - f1);
    hi = *reinterpret_cast<uint32_t*>(&h);
    lo = *reinterpret_cast<uint32_t*>(&g);
}

// ---------------- weight preconvert kernel (fragment-order output) ----------------
__global__ __launch_bounds__(256) void convert_kernel(
    const float* __restrict__ Wf1, const float* __restrict__ Wf2,
    const float* __restrict__ Wc1, const float* __restrict__ Wb1,
    const float* __restrict__ Wc2)
{
    int tid = threadIdx.x;
    if (blockIdx.x < 64) {
        int idx = blockIdx.x * 256 + tid;        // ((m*8+K)*16+s)*32+lane
        int lane = idx & 31;
        int rest = idx >> 5;
        int s = rest & 15;
        int K = (rest >> 4) & 7;
        int m = rest >> 7;
        int ql = lane & 3, gid = lane >> 2;
        int n  = s * 8 + gid;
        int k0 = K * 16 + 2 * ql;
        const float* src = (m == 0) ? Wf1 : (m == 1) ? Wf2 : (m == 2) ? Wc1 : Wb1;
        float v0 = 0.f, v1 = 0.f, v2 = 0.f, v3 = 0.f;
        if (m != 0) {
            v0 = src[k0 * 128 + n];       v1 = src[(k0 + 1) * 128 + n];
            v2 = src[(k0 + 8) * 128 + n]; v3 = src[(k0 + 9) * 128 + n];
        } else {
            if (k0     < 68) v0 = src[k0 * 128 + n];
            if (k0 + 1 < 68) v1 = src[(k0 + 1) * 128 + n];
            if (k0 + 8 < 68) v2 = src[(k0 + 8) * 128 + n];
            if (k0 + 9 < 68) v3 = src[(k0 + 9) * 128 + n];
        }
        uint32_t bh0, bl0, bh1, bl1;
        split2(v0, v1, bh0, bl0);
        split2(v2, v3, bh1, bl1);
        g_bfrag[idx] = make_uint4(bh0, bh1, bl0, bl1);
    } else if (tid < 128) {
        float s[6] = {0, 0, 0, 0, 0, 0};
        const float4* w4 = (const float4*)(Wc2 + tid * 48);
        #pragma unroll
        for (int v = 0; v < 12; v++) {
            float4 f = w4[v];
            s[(v * 4 + 0) % 6] += f.x; s[(v * 4 + 1) % 6] += f.y;
            s[(v * 4 + 2) % 6] += f.z; s[(v * 4 + 3) % 6] += f.w;
        }
        #pragma unroll
        for (int k = 0; k < 6; k++) g_wc2bar[tid * 8 + k] = s[k] * 0.125f;
        g_wc2bar[tid * 8 + 6] = 0.f; g_wc2bar[tid * 8 + 7] = 0.f;
    }
}

// one layer: B frags direct from global (8 LDG.128/warp), A frags via ldmatrix
template<int KS>
__device__ __forceinline__ void mma_layer(float acc[3][4],
                                          uint32_t aH, uint32_t aL,
                                          const uint4* __restrict__ frag,
                                          int lr, int lc, int lane)
{
    uint4 B[KS];
    #pragma unroll
    for (int K = 0; K < KS; K++) B[K] = frag[K * 512 + lane];
    uint32_t base = (uint32_t)(lr * WP + lc * 2);
    #pragma unroll
    for (int K = 0; K < KS; K++) {
        uint32_t ah[4], al[4];
        ldm4(ah, aH + base + K * 32);
        ldm4(al, aL + base + K * 32);
        mma_bf16(acc[0], ah, B[K].x, B[K].y);
        mma_bf16(acc[1], ah, B[K].z, B[K].w);
        mma_bf16(acc[2], al, B[K].x, B[K].y);
    }
}

// bias+relu -> bf16 hi/lo act buffer (8-col slice); reset accs
__device__ __forceinline__ void epi_act(float acc[3][4], const float* __restrict__ bias,
                                        char* smem, int offH, int offL,
                                        int w, int lane)
{
    int r0 = lane >> 2, ql = lane & 3;
    int c = w * 8 + 2 * ql;
    float2 b = *(const float2*)(bias + c);
    float v0 = fmaxf(acc[0][0] + acc[1][0] + acc[2][0] + b.x, 0.f);
    float v1 = fmaxf(acc[0][1] + acc[1][1] + acc[2][1] + b.y, 0.f);
    float v2 = fmaxf(acc[0][2] + acc[1][2] + acc[2][2] + b.x, 0.f);
    float v3 = fmaxf(acc[0][3] + acc[1][3] + acc[2][3] + b.y, 0.f);
    uint32_t h0, l0, h1, l1;
    split2(v0, v1, h0, l0);
    split2(v2, v3, h1, l1);
    *(uint32_t*)(smem + offH + r0 * WP + c * 2)       = h0;
    *(uint32_t*)(smem + offL + r0 * WP + c * 2)       = l0;
    *(uint32_t*)(smem + offH + (r0 + 8) * WP + c * 2) = h1;
    *(uint32_t*)(smem + offL + (r0 + 8) * WP + c * 2) = l1;
    #pragma unroll
    for (int p = 0; p < 3; p++)
        acc[p][0] = acc[p][1] = acc[p][2] = acc[p][3] = 0.f;
}

__global__ __launch_bounds__(NTHR, 1) void mlp_kernel(
    const float* __restrict__ x,
    const float* __restrict__ budget,
    const float* __restrict__ emb_id, const float* __restrict__ emb_period,
    const float* __restrict__ emb_time,
    const float* __restrict__ bf1, const float* __restrict__ bf2,
    const float* __restrict__ bc1, const float* __restrict__ bc2,
    const float* __restrict__ bb1, const float* __restrict__ Wb2,
    const float* __restrict__ bb2,
    float* __restrict__ out)
{
    extern __shared__ char smem[];
    float* smf = (float*)smem;
    const int tid  = threadIdx.x;
    const int w    = tid >> 5;
    const int lane = tid & 31;
    const int lr   = lane & 15;
    const int lc   = (lane >> 4) * 8;
    const int r0l  = lane >> 2;
    const int ql   = lane & 3;
    const int row0 = blockIdx.x * RPB;
    const uint32_t smb = (uint32_t)__cvta_generic_to_shared(smem);
    const uint4* fragW = g_bfrag + w * 32;   // + m*4096 per layer, + K*512 per kstep

    // ======== PDL-independent prologue (runs while convert_kernel finishes) ====
    if (tid < 48) {
        int r = tid / 3, c = tid - r * 3;
        ((int*)(smem + OIX))[r * 3 + c] = (int)x[(row0 + r) * XCOLS + c];
    }
    // budget prefetch -> registers (hides behind the MLP)
    const float4* bud4 = (const float4*)budget + row0 * 128;
    float4 pf[4];
    #pragma unroll
    for (int it = 0; it < 4; it++) pf[it] = bud4[tid + it * NTHR];

    // zero E hi/lo (covers zero-pad cols 68..135); 544 uint4
    if (tid < 544) ((uint4*)(smem + E_H))[tid] = make_uint4(0, 0, 0, 0);
    if (tid < 32)  ((uint4*)(smem + E_H))[512 + tid] = make_uint4(0, 0, 0, 0);

    // biases (harness inputs, independent of convert)
    if (tid < 128) {
        smf[OB1 / 4 + tid] = bf1[tid];
        smf[OB2 / 4 + tid] = bf2[tid];
        smf[OB3 / 4 + tid] = bc1[tid];
        smf[OB4 / 4 + tid] = bb1[tid];
        smf[OWB / 4 + tid] = Wb2[tid];
    } else if (tid < 134) {
        int t = tid - 128;
        float s = 0.f;
        #pragma unroll
        for (int j = 0; j < 8; j++) s += bc2[j * 6 + t];
        smf[OBC / 4 + t] = s * 0.125f;
    } else if (tid == 134) {
        smf[OBC / 4 + 6] = bb2[0];
    }
    __syncthreads();   // E zeros + indices visible

    // emb fill: row = tid>>5, cols lane, lane+32, lane+64 (div-free)
    {
        const int* ix = (const int*)(smem + OIX);
        int r = tid >> 5;
        int i0 = ix[r * 3 + 0], i1 = ix[r * 3 + 1], i2 = ix[r * 3 + 2];
        #pragma unroll
        for (int jj = 0; jj < 3; jj++) {
            int c = lane + jj * 32;
            if (c < 68) {
                float v;
                if      (c < 8)  v = emb_id    [i1 * 8  + c];
                else if (c < 16) v = emb_period[i0 * 8  + (c - 8)];
                else if (c < 32) v = emb_time  [i2 * 16 + (c - 16)];
                else             v = x[(row0 + r) * XCOLS + 3 + (c - 32)];
                __nv_bfloat16 h = __float2bfloat16(v);
                __nv_bfloat16 l = __float2bfloat16(v - __bfloat162float(h));
                *(__nv_bfloat16*)(smem + E_H + r * WP + c * 2) = h;
                *(__nv_bfloat16*)(smem + E_L + r * WP + c * 2) = l;
            }
        }
    }

    // ======== wait for convert_kernel's fragment weights ========
    cudaGridDependencySynchronize();

    if (tid < 256)
        ((float4*)(smem + OW2))[tid] = ((const float4*)g_wc2bar)[tid];
    __syncthreads();   // emb + OW2 visible

    float acc[3][4];
    #pragma unroll
    for (int p = 0; p < 3; p++)
        acc[p][0] = acc[p][1] = acc[p][2] = acc[p][3] = 0.f;

    // ---- L1: E x Wf1 -> actA ----
    mma_layer<5>(acc, smb + E_H, smb + E_L, fragW, lr, lc, lane);
    epi_act(acc, smf + OB1 / 4, smem, AAH, AAL, w, lane);
    __syncthreads();

    // ---- L2: actA x Wf2 -> actB ----
    mma_layer<8>(acc, smb + AAH, smb + AAL, fragW + 4096, lr, lc, lane);
    epi_act(acc, smf + OB2 / 4, smem, ABH, ABL, w, lane);
    __syncthreads();

    // ---- L3: actB x Wc1 -> cbar partials (fragment-direct) ----
    mma_layer<8>(acc, smb + ABH, smb + ABL, fragW + 2 * 4096, lr, lc, lane);
    {
        int c0 = w * 8 + 2 * ql;
        float2 b = *(const float2*)(smf + OB3 / 4 + c0);
        float v00 = fmaxf(acc[0][0] + acc[1][0] + acc[2][0] + b.x, 0.f);
        float v01 = fmaxf(acc[0][1] + acc[1][1] + acc[2][1] + b.y, 0.f);
        float v10 = fmaxf(acc[0][2] + acc[1][2] + acc[2][2] + b.x, 0.f);
        float v11 = fmaxf(acc[0][3] + acc[1][3] + acc[2][3] + b.y, 0.f);
        const float* w0p = smf + OW2 / 4 + c0 * 8;
        const float* w1p = w0p + 8;
        float p0[6], p1[6];
        #pragma unroll
        for (int k = 0; k < 6; k++) {
            p0[k] = v00 * w0p[k] + v01 * w1p[k];
            p1[k] = v10 * w0p[k] + v11 * w1p[k];
        }
        #pragma unroll
        for (int k = 0; k < 6; k++) {
            p0[k] += __shfl_xor_sync(0xffffffff, p0[k], 1);
            p0[k] += __shfl_xor_sync(0xffffffff, p0[k], 2);
            p1[k] += __shfl_xor_sync(0xffffffff, p1[k], 1);
            p1[k] += __shfl_xor_sync(0xffffffff, p1[k], 2);
        }
        if (ql == 0) {
            float* d0 = smf + OPC / 4 + (w * 16 + r0l) * 6;
            float* d1 = smf + OPC / 4 + (w * 16 + r0l + 8) * 6;
            #pragma unroll
            for (int k = 0; k < 6; k++) { d0[k] = p0[k]; d1[k] = p1[k]; }
        }
        #pragma unroll
        for (int p = 0; p < 3; p++)
            acc[p][0] = acc[p][1] = acc[p][2] = acc[p][3] = 0.f;
    }
    // NO barrier: L4 re-reads the unchanged actB smem; OPC consumed after next sync

    // ---- L4: actB x Wb1 -> sbase partials ----
    mma_layer<8>(acc, smb + ABH, smb + ABL, fragW + 3 * 4096, lr, lc, lane);
    {
        int c0 = w * 8 + 2 * ql;
        float2 b  = *(const float2*)(smf + OB4 / 4 + c0);
        float2 wv = *(const float2*)(smf + OWB / 4 + c0);
        float s0 = fmaxf(acc[0][0] + acc[1][0] + acc[2][0] + b.x, 0.f) * wv.x
                 + fmaxf(acc[0][1] + acc[1][1] + acc[2][1] + b.y, 0.f) * wv.y;
        float s1 = fmaxf(acc[0][2] + acc[1][2] + acc[2][2] + b.x, 0.f) * wv.x
                 + fmaxf(acc[0][3] + acc[1][3] + acc[2][3] + b.y, 0.f) * wv.y;
        s0 += __shfl_xor_sync(0xffffffff, s0, 1);
        s0 += __shfl_xor_sync(0xffffffff, s0, 2);
        s1 += __shfl_xor_sync(0xffffffff, s1, 1);
        s1 += __shfl_xor_sync(0xffffffff, s1, 2);
        if (ql == 0) {
            smf[OPB / 4 + w * 16 + r0l]     = s0;
            smf[OPB / 4 + w * 16 + r0l + 8] = s1;
        }
    }
    __syncthreads();   // OPC + OPB visible

    // ---- fused combine + cubic (48 threads) + sbase combine (16 threads) ----
    if (tid < 48) {
        int rb = tid / 3, m = tid - rb * 3;
        float cb[4];
        #pragma unroll
        for (int j = 0; j < 4; j++) {
            float s = smf[OBC / 4 + m + j];
            #pragma unroll
            for (int ww = 0; ww < 16; ww++)
                s += smf[OPC / 4 + (ww * 16 + rb) * 6 + m + j];
            cb[j] = s;
        }
        float c0 = cb[0], c1 = cb[1], c2 = cb[2], c3 = cb[3];
        const float k6 = 1.f / 6.f;
        float A0 = (c0 + 4.f * c1 + c2) * k6;
        float A1 = (c2 - c0) * 0.5f;
        float A2 = (c0 - 2.f * c1 + c2) * 0.5f;
        float A3 = (c3 - c0 + 3.f * (c1 - c2)) * k6;
        float d  = 1.5f - (float)m;
        float B0 = A0 + d * (A1 + d * (A2 + d * A3));
        float B1 = 1.5f * (A1 + d * (2.f * A2 + 3.f * A3 * d));
        float B2 = 2.25f * (A2 + 3.f * A3 * d);
        float B3 = 3.375f * A3;
        ((float4*)(smem + OCF))[rb * 4 + m] = make_float4(B0, B1, B2, B3);
    } else if (tid < 64) {
        int rb = tid - 48;
        float s = smf[OBC / 4 + 6];
        #pragma unroll
        for (int ww = 0; ww < 16; ww++)
            s += smf[OPB / 4 + ww * 16 + rb];
        smf[OSB / 4 + rb] = s;
    }
    __syncthreads();

    // ---- budget phase: data already in pf[] registers ----
    float4* out4 = (float4*)out + row0 * 128;
    const float4* cb4 = (const float4*)(smem + OCF);
    #pragma unroll
    for (int it = 0; it < 4; it++) {
        int q = tid + it * NTHR;
        int row = q >> 7;
        float4 bv = pf[it];
        float sb = smf[OSB / 4 + row];
        float xs[4] = {bv.x, bv.y, bv.z, bv.w};
        float o[4];
        #pragma unroll
        for (int e = 0; e < 4; e++) {
            float X = xs[e];
            float tp = fmaf(X, 1.5f, 1.5f);
            int m = min((int)tp, 2);
            float4 B = cb4[row * 4 + m];
            float sp = fmaf(fmaf(fmaf(B.w, X, B.z), X, B.y), X, B.x);
            float u = X * X;
            float P = fmaf(u, fmaf(u, fmaf(u, fmaf(u, 2.1357286e-5f, -2.1081349e-4f),
                                           2.0833333e-3f), -2.0833333e-2f), 0.25f);
            float sil = X * fmaf(X, P, 0.5f);
            o[e] = sb * (sil + sp);
        }
        out4[q] = make_float4(o[0], o[1], o[2], o[3]);
    }
}

extern "C" void kernel_launch(void* const* d_in, const int* in_sizes, int n_in,
                              void* d_out, int out_size)
{
    const float* x          = (const float*)d_in[0];
    const float* budget     = (const float*)d_in[1];
    const float* emb_id     = (const float*)d_in[2];
    const float* emb_period = (const float*)d_in[3];
    const float* emb_time   = (const float*)d_in[4];
    const float* Wf1 = (const float*)d_in[5];
    const float* bf1 = (const float*)d_in[6];
    const float* Wf2 = (const float*)d_in[7];
    const float* bf2 = (const float*)d_in[8];
    const float* Wc1 = (const float*)d_in[9];
    const float* bc1 = (const float*)d_in[10];
    const float* Wc2 = (const float*)d_in[11];
    const float* bc2 = (const float*)d_in[12];
    // d_in[13..16] = Ws1/bs1/Ws2/bs2 : unused in reference output
    const float* Wb1 = (const float*)d_in[17];
    const float* bb1 = (const float*)d_in[18];
    const float* Wb2 = (const float*)d_in[19];
    const float* bb2 = (const float*)d_in[20];

    cudaFuncSetAttribute(mlp_kernel, cudaFuncAttributeMaxDynamicSharedMemorySize, MLP_SMEM);

    convert_kernel<<<65, 256>>>(Wf1, Wf2, Wc1, Wb1, Wc2);

    // PDL launch: mlp starts while convert drains; prologue runs pre-sync
    cudaLaunchConfig_t cfg = {};
    cfg.gridDim = dim3(NCTA);
    cfg.blockDim = dim3(NTHR);
    cfg.dynamicSmemBytes = MLP_SMEM;
    cfg.stream = 0;
    cudaLaunchAttribute attrs[1];
    attrs[0].id = cudaLaunchAttributeProgrammaticStreamSerialization;
    attrs[0].val.programmaticStreamSerializationAllowed = 1;
    cfg.attrs = attrs;
    cfg.numAttrs = 1;
    cudaLaunchKernelEx(&cfg, mlp_kernel,
                       x, budget, emb_id, emb_period, emb_time,
                       bf1, bf2, bc1, bc2, bb1, Wb2, bb2, (float*)d_out);
}